// round 4
// baseline (speedup 1.0000x reference)
#include <cuda_runtime.h>

#define BATCHN 256
#define SEQN   1024
#define HIDN   200
#define VOCABN 33

#define NGW   25            // GEMV warps
#define NGT   (NGW*32)      // 800 GEMV threads
#define NLOG  (2*VOCABN)    // 66 logits threads
#define TPB   896           // 28 warps
#define WOTP  36            // wotc pad: (4i+v) spreads banks

__device__ float d_E2[VOCABN * HIDN];
__device__ int   d_x_is32;

// ---------------------------------------------------------------------------
__global__ void prep_kernel(const float* __restrict__ emb,
                            const float* __restrict__ We,
                            const int* __restrict__ x32) {
    int v = blockIdx.x, j = threadIdx.x;
    if (v == 0 && j == 0) {
        int is32 = 0;
        for (int i = 0; i < 128; i++)
            if (x32[2 * i + 1] != 0) is32 = 1;
        d_x_is32 = is32;
    }
    float acc = 0.f;
#pragma unroll 8
    for (int e = 0; e < HIDN; e++)
        acc += emb[v * HIDN + e] * We[e * HIDN + j];
    d_E2[v * HIDN + j] = acc;
}

// ---------------------------------------------------------------------------
struct __align__(16) Smem {
    float4 hdup[2][HIDN];        // [parity][col] = {h_r0,h_r0,h_r1,h_r1}
    float2 hpair[2][HIDN];       // [parity][col] = {h_r0,h_r1}
    float2 lp[2][VOCABN][2];     // logits partials [parity][v][half]
    float  e2[VOCABN * HIDN];
    float  wotc[HIDN * WOTP];    // W_o i-major padded: wotc[i*36+v]
    int    xi[2][SEQN];
};

union F2U { unsigned long long u; float2 f2; };

__device__ __forceinline__ void fma2(unsigned long long& d,
                                     unsigned long long a,
                                     unsigned long long b) {
    asm("fma.rn.f32x2 %0, %1, %2, %0;" : "+l"(d) : "l"(a), "l"(b));
}

__device__ __forceinline__ float fast_tanh(float x) {
    float e = __expf(2.0f * x);
    return 1.0f - __fdividef(2.0f, e + 1.0f);
}

extern __shared__ unsigned char smem_raw[];

__global__ void __launch_bounds__(TPB, 1)
scan_kernel(const void* __restrict__ xv,
            const float* __restrict__ hidden,
            const float* __restrict__ Wh,
            const float* __restrict__ Wo,
            float* __restrict__ out_logits,
            float* __restrict__ out_hidden,
            int write_h) {
    Smem& s = *reinterpret_cast<Smem*>(smem_raw);
    const int tid  = threadIdx.x;
    const int b0   = blockIdx.x * 2;
    const int lane = tid & 31;

    // ---- setup ----
    for (int k = tid; k < VOCABN * HIDN; k += TPB) s.e2[k] = d_E2[k];
    for (int k = tid; k < VOCABN * HIDN; k += TPB) {
        int i = k / VOCABN, v = k % VOCABN;
        s.wotc[i * WOTP + v] = Wo[i * VOCABN + v];
    }
    {
        const int is32 = d_x_is32;
        const int* __restrict__ x32 = (const int*)xv;
        const long long* __restrict__ x64 = (const long long*)xv;
        for (int k = tid; k < 2 * SEQN; k += TPB) {
            int r = k >> 10, t = k & (SEQN - 1);
            long long idx = is32 ? (long long)x32[(size_t)(b0 + r) * SEQN + t]
                                 : x64[(size_t)(b0 + r) * SEQN + t];
            s.xi[r][t] = (int)idx;
        }
    }
    for (int j = tid; j < HIDN; j += TPB) {
        float a = hidden[(size_t)b0 * HIDN + j];
        float b = hidden[(size_t)(b0 + 1) * HIDN + j];
        s.hdup[0][j] = make_float4(a, a, b, b);
    }

    // ---- GEMV geometry: warp w, group g (colpair), chunk q (i-range) ----
    const int w  = tid >> 5;
    const int g  = lane >> 3;          // 0..3
    const int q  = lane & 7;           // 0..7
    const int cp = w * 4 + g;          // colpair 0..99
    const int i0 = q * 25;

    unsigned long long wreg[25];
    if (tid < NGT) {
        const float* wp = Wh + (size_t)i0 * HIDN + 2 * cp;
#pragma unroll
        for (int ii = 0; ii < 25; ii++)
            wreg[ii] = *reinterpret_cast<const unsigned long long*>(wp + (size_t)ii * HIDN);
    }

    // post-reduce role for lanes q<4: (row, colsel)
    const int rrow = q & 1;
    const int rcs  = q >> 1;
    const int rcol = 2 * cp + rcs;

    // logits mapping: tids 800..865 -> (v, half)
    const int lk = tid - NGT;
    const int lv = (lk >= 0) ? lk >> 1 : 0;
    const int lh = lk & 1;
    const bool is_log = (lk >= 0 && lk < NLOG);

    __syncthreads();

    for (int t = 0; t <= SEQN + 1; t++) {
        if (tid < NGT && t < SEQN) {
            const int rb = t & 1, wb = rb ^ 1;
            // dot-product partials: 25 x (LDS.128 + 2 FMA2)
            F2U a0, a1;
            a0.u = a1.u = 0ull;
            const ulonglong2* hp =
                reinterpret_cast<const ulonglong2*>(&s.hdup[rb][i0]);
#pragma unroll
            for (int ii = 0; ii < 25; ii++) {
                ulonglong2 hd = hp[ii];
                fma2(a0.u, wreg[ii], hd.x);   // row 0, cols {2cp,2cp+1}
                fma2(a1.u, wreg[ii], hd.y);   // row 1
            }
            // butterfly reduce over the 8 i-chunks (lanes q=0..7)
            float a0x = a0.f2.x, a0y = a0.f2.y, a1x = a1.f2.x, a1y = a1.f2.y;
#pragma unroll
            for (int k = 1; k < 8; k <<= 1) {
                a0x += __shfl_xor_sync(0xffffffffu, a0x, k);
                a0y += __shfl_xor_sync(0xffffffffu, a0y, k);
                a1x += __shfl_xor_sync(0xffffffffu, a1x, k);
                a1y += __shfl_xor_sync(0xffffffffu, a1y, k);
            }
            if (q < 4) {
                float val = rrow ? (rcs ? a1y : a1x) : (rcs ? a0y : a0x);
                float xw  = s.e2[s.xi[rrow][t] * HIDN + rcol];
                float h   = fast_tanh(val + xw);
                F2U hh; hh.f2 = make_float2(h, h);
                *reinterpret_cast<unsigned long long*>(
                    reinterpret_cast<char*>(&s.hdup[wb][rcol]) + rrow * 8) = hh.u;
                reinterpret_cast<float*>(&s.hpair[t & 1][rcol])[rrow] = h;
            }
        } else if (is_log) {
            // partials for h_{t-1}
            if (t >= 1 && t <= SEQN) {
                const int ph = (t - 1) & 1;
                F2U lacc; lacc.u = 0ull;
                const float* wp = &s.wotc[(lh * 100) * WOTP + lv];
                const unsigned long long* hpp =
                    reinterpret_cast<const unsigned long long*>(&s.hpair[ph][lh * 100]);
#pragma unroll 10
                for (int ii = 0; ii < 100; ii++) {
                    float wv = wp[ii * WOTP];
                    F2U wd; wd.f2 = make_float2(wv, wv);
                    fma2(lacc.u, hpp[ii], wd.u);
                }
                s.lp[t & 1][lv][lh] = lacc.f2;
            }
            // finalize logits for h_{t-2}
            if (t >= 2) {
                const int pf = (t - 1) & 1;
                float2 p0 = s.lp[pf][lv][0];
                float2 p1 = s.lp[pf][lv][1];
                float L = lh ? (p0.y + p1.y) : (p0.x + p1.x);
                out_logits[(size_t)(b0 + lh) * SEQN * VOCABN
                           + (size_t)(t - 2) * VOCABN + lv] = L;
            }
        }
        __syncthreads();
    }

    // ---- final hidden: h_{SEQN-1} in hpair[(SEQN-1)&1] ----
    if (write_h && tid < 2 * HIDN) {
        const int fc = tid % HIDN, fr = tid / HIDN;
        out_hidden[(size_t)(b0 + fr) * HIDN + fc] =
            reinterpret_cast<const float*>(&s.hpair[(SEQN - 1) & 1][fc])[fr];
    }
}

// ---------------------------------------------------------------------------
extern "C" void kernel_launch(void* const* d_in, const int* in_sizes, int n_in,
                              void* d_out, int out_size) {
    const void*  x      = d_in[0];
    const float* hidden = (const float*)d_in[1];
    const float* emb    = (const float*)d_in[2];
    const float* We     = (const float*)d_in[3];
    const float* Wh     = (const float*)d_in[4];
    const float* Wo     = (const float*)d_in[5];

    float* logits = (float*)d_out;
    const long long LOGITS_ELEMS = (long long)BATCHN * SEQN * VOCABN;
    int write_h = (out_size >= (int)(LOGITS_ELEMS + BATCHN * HIDN));
    float* outh = logits + LOGITS_ELEMS;

    prep_kernel<<<VOCABN, HIDN>>>(emb, We, (const int*)x);

    cudaFuncSetAttribute((const void*)scan_kernel,
                         cudaFuncAttributeMaxDynamicSharedMemorySize,
                         (int)sizeof(Smem));
    scan_kernel<<<BATCHN / 2, TPB, sizeof(Smem)>>>(
        x, hidden, Wh, Wo, logits, outh, write_h);
}